// round 3
// baseline (speedup 1.0000x reference)
#include <cuda_runtime.h>

// GCBFSafetyLayer: L_g_h = dh_dx @ g is identically zero (the nonzero state
// columns of dh_dx [position jacobian, cols 0..1] meet only the zero rows of
// g [rows 0..1]; the I/MASS rows of g [rows 2..3] meet the zero columns of
// dh_dx). So in project(), an = ||a||^2 = 0 fails the (an > 1e-6) gate for
// every constraint on every iteration -> u never changes -> safe_action ==
// raw_action bit-exact. Kernel = copy d_in[3] (65536 f32 = 16384 float4).
//
// We are at the launch-overhead floor (T_ovh ~5000 cyc + graph replay);
// this round trades CTA count for per-thread MLP: 64 CTAs x 128 threads,
// 2 independent float4 loads per thread (both issued before either store
// dependency binds), halving CTA-distribution tail at equal total MLP.

__global__ __launch_bounds__(128, 1)
void gcbf_copy_kernel(const float4* __restrict__ src, float4* __restrict__ dst) {
    int i = blockIdx.x * 128 + threadIdx.x;
    float4 a = src[i];
    float4 b = src[i + 8192];
    dst[i] = a;
    dst[i + 8192] = b;
}

extern "C" void kernel_launch(void* const* d_in, const int* in_sizes, int n_in,
                              void* d_out, int out_size) {
    // inputs: [0] positions, [1] velocities, [2] obstacles, [3] raw_action
    gcbf_copy_kernel<<<64, 128>>>((const float4*)d_in[3], (float4*)d_out);
}

// round 4
// speedup vs baseline: 1.0694x; 1.0694x over previous
#include <cuda_runtime.h>

// GCBFSafetyLayer: L_g_h = dh_dx @ g is identically zero (the nonzero state
// columns of dh_dx [position jacobian, cols 0..1] meet only the zero rows of
// g [rows 0..1]; the I/MASS rows of g [rows 2..3] meet the zero columns of
// dh_dx). So in project(), an = ||a||^2 = 0 fails the (an > 1e-6) gate for
// every constraint on every iteration -> u never changes -> safe_action ==
// raw_action bit-exact. Kernel = copy d_in[3] (65536 f32 = 16384 float4).
//
// R3 post-mortem: 2-loads/thread @ 64 CTAs regressed (fewer SMs covering the
// single DRAM round trip). Best measured config is R2: 128 CTAs x 128 threads,
// one float4 per thread, regs=16 — at the launch-overhead floor
// (T_ovh ~5000 cyc + graph replay; DRAM at 0.8% of peak).

__global__ __launch_bounds__(128, 1)
void gcbf_copy_kernel(const float4* __restrict__ src, float4* __restrict__ dst) {
    int i = blockIdx.x * 128 + threadIdx.x;
    dst[i] = src[i];
}

extern "C" void kernel_launch(void* const* d_in, const int* in_sizes, int n_in,
                              void* d_out, int out_size) {
    // inputs: [0] positions, [1] velocities, [2] obstacles, [3] raw_action
    gcbf_copy_kernel<<<128, 128>>>((const float4*)d_in[3], (float4*)d_out);
}